// round 15
// baseline (speedup 1.0000x reference)
#include <cuda_runtime.h>
#include <cuda_bf16.h>
#include <math.h>

#define BB 32
#define LL 2048
#define HH 8
#define DMET 16
#define SDIM 27
#define DM 256
#define NLAYERS 4
#define DS 64
#define TE 256
#define LT 2055          // LL + HH - 1
#define LTP 2056         // padded row stride for g_h
#define LTT 2112         // 33*64 padded yT rows
#define FIN 44
#define NT 1056          // 33 l-tiles * 32 batches

typedef unsigned long long ull;
typedef unsigned int u32;

// ---------------- scratch (device globals; no allocation) ----------------
__device__ float g_h[(size_t)BB * DM * LTP];        // activations (pre-BN) [b][d][l]
__device__ u32 g_yh[(size_t)BB * LTT * 128];        // scan out, bf16-hi, [b][l][d/2] packed
__device__ u32 g_yl[(size_t)BB * LTT * 128];        // bf16-lo plane
__device__ u32 g_wh[NLAYERS][512 * 128];            // W^T split [layer][e][d/2] packed
__device__ u32 g_wl[NLAYERS][512 * 128];
__device__ float g_tb[BB * DM];
__device__ float g_mean[DM], g_rstd[DM];
__device__ float g_bnp0[DM * NT], g_bnp1[DM * NT];

#define SCAN_SMEM (155776)   // 32 warps * 16*68 f32 (sp) + 32*129 f32 (stage)
#define GEMM_SMEM (55296)    // 13824 u32

// ---------------- f32x2 packed math ----------------
__device__ __forceinline__ ull pk2(float a, float b) {
    ull r; asm("mov.b64 %0,{%1,%2};" : "=l"(r) : "f"(a), "f"(b)); return r;
}
__device__ __forceinline__ void up2(ull v, float& a, float& b) {
    asm("mov.b64 {%0,%1},%2;" : "=f"(a), "=f"(b) : "l"(v));
}
__device__ __forceinline__ ull f2fma(ull a, ull b, ull c) {
    ull d; asm("fma.rn.f32x2 %0,%1,%2,%3;" : "=l"(d) : "l"(a), "l"(b), "l"(c)); return d;
}
__device__ __forceinline__ ull f2mul(ull a, ull b) {
    ull d; asm("mul.rn.f32x2 %0,%1,%2;" : "=l"(d) : "l"(a), "l"(b)); return d;
}
__device__ __forceinline__ ull f2add(ull a, ull b) {
    ull d; asm("add.rn.f32x2 %0,%1,%2;" : "=l"(d) : "l"(a), "l"(b)); return d;
}

// ---------------- helpers ----------------
__device__ __forceinline__ float sigm(float x) { return 1.f / (1.f + __expf(-x)); }
__device__ __forceinline__ float gelu_tanh(float v) {
    float v3 = v * v * v;
    float w = 1.5957691216057308f * fmaf(0.044715f, v3, v);
    return v * sigm(w);
}
__device__ __forceinline__ u32 bfsplit(float x, u32& lo) {
    __nv_bfloat16 h = __float2bfloat16(x);
    float r = x - __bfloat162float(h);
    __nv_bfloat16 l = __float2bfloat16(r);
    lo = (u32)__bfloat16_as_ushort(l);
    return (u32)__bfloat16_as_ushort(h);
}
__device__ __forceinline__ void mma16816(float* c, const u32* a, const u32* b) {
    asm volatile(
        "mma.sync.aligned.m16n8k16.row.col.f32.bf16.bf16.f32 "
        "{%0,%1,%2,%3},{%4,%5,%6,%7},{%8,%9},{%0,%1,%2,%3};"
        : "+f"(c[0]), "+f"(c[1]), "+f"(c[2]), "+f"(c[3])
        : "r"(a[0]), "r"(a[1]), "r"(a[2]), "r"(a[3]), "r"(b[0]), "r"(b[1]));
}

// ---------------- time MLP ----------------
__global__ void k_timemlp(const float* __restrict__ t, const float* __restrict__ freqs,
                          const float* __restrict__ phases,
                          const float* __restrict__ W1, const float* __restrict__ b1,
                          const float* __restrict__ W2, const float* __restrict__ b2) {
    int b = blockIdx.x, tid = threadIdx.x;
    __shared__ float tf[TE];
    __shared__ float hid[2 * TE];
    float tv = t[b];
    tf[tid] = cosf(fmaf(tv, freqs[tid], phases[tid])) * 1.41421356237309515f;
    __syncthreads();
    for (int j = tid; j < 2 * TE; j += 256) {
        float acc = b1[j];
        #pragma unroll 8
        for (int k = 0; k < TE; ++k) acc = fmaf(tf[k], W1[k * 512 + j], acc);
        hid[j] = acc * sigm(acc);
    }
    __syncthreads();
    float acc = b2[tid];
    #pragma unroll 8
    for (int k = 0; k < 2 * TE; ++k) acc = fmaf(hid[k], W2[k * 256 + tid], acc);
    g_tb[b * DM + tid] = acc;
}

// ---------------- input projection ----------------
__global__ void k_inproj(const float* __restrict__ xp, const float* __restrict__ noisy,
                         const float* __restrict__ xf, const float* __restrict__ sa,
                         const float* __restrict__ inW, const float* __restrict__ inb) {
    int b = blockIdx.z, dt = blockIdx.y, ltile = blockIdx.x;
    int tid = threadIdx.x;
    int ll = tid & 31, dl = tid >> 5;
    int l0 = ltile * 32, d0 = dt * 8;
    __shared__ float sf[32][45];
    __shared__ float sw[FIN][8];
    for (int i = tid; i < 32 * FIN; i += 256) {
        int li = i / FIN, f = i % FIN;
        int l = l0 + li;
        float v = 0.f;
        if (l < LT) {
            if (f < DMET)
                v = (l < LL) ? xp[((size_t)b * LL + l) * DMET + f]
                             : xf[((size_t)b * (HH - 1) + (l - LL)) * DMET + f];
            else if (f == DMET)
                v = (l >= LL - 1) ? noisy[b * HH + (l - (LL - 1))] : 0.f;
            else
                v = sa[b * SDIM + (f - DMET - 1)];
        }
        sf[li][f] = v;
    }
    for (int i = tid; i < FIN * 8; i += 256) {
        int f = i >> 3, c = i & 7;
        sw[f][c] = inW[f * DM + d0 + c];
    }
    __syncthreads();
    int l = l0 + ll, d = d0 + dl;
    float acc = inb[d];
    #pragma unroll
    for (int f = 0; f < FIN; ++f) acc = fmaf(sf[ll][f], sw[f][dl], acc);
    if (l >= LL - 1) acc += g_tb[b * DM + d];
    if (l < LT) g_h[((size_t)b * DM + d) * LTP + l] = acc;
}

// ---------------- weight transpose + bf16 split (ALL layers, one launch) -----------
__global__ void k_wprep(const float* __restrict__ W) {
    int idx = blockIdx.x * 256 + threadIdx.x;   // 0..262143
    int layer = idx >> 16;
    int r = idx & 65535;
    int e = r & 511, kp = r >> 9;               // kp 0..127
    const float* Wl = W + (size_t)layer * DM * 2 * DM;
    float x0 = Wl[(2 * kp) * 512 + e];
    float x1 = Wl[(2 * kp + 1) * 512 + e];
    u32 lo0, lo1;
    u32 h0 = bfsplit(x0, lo0);
    u32 h1 = bfsplit(x1, lo1);
    g_wh[layer][e * 128 + kp] = h0 | (h1 << 16);
    g_wl[layer][e * 128 + kp] = lo0 | (lo1 << 16);
}

// ---- SSM scan: 32 warps = 32 d; packed STS.64 partials, f32x2 reduction -----------
extern "C" __global__ void __launch_bounds__(1024) k_scan(
        const float* __restrict__ log_dt, const float* __restrict__ Are,
        const float* __restrict__ Aim, const float* __restrict__ Cre,
        const float* __restrict__ Cim, const float* __restrict__ Dv,
        const float* __restrict__ pg, const float* __restrict__ pb, int apply_bn) {
    extern __shared__ float dyn[];
    int warp = threadIdx.x >> 5, lane = threadIdx.x & 31;
    float* sp = dyn + warp * 1088;          // [16 step][68] per warp (pairs packed)
    float* stage = dyn + 32 * 1088;         // [32 d][129]
    int b = blockIdx.x >> 3, dbase = (blockIdx.x & 7) * 32;
    int d = dbase + warp;
    float mean = 0.f, scl = 1.f, bet = 0.f;
    if (apply_bn) { mean = g_mean[d]; scl = g_rstd[d] * pg[d]; bet = pb[d]; }
    float dt = __expf(log_dt[d]);
    float a0r, a0i, c0kr, c0ki, a1r, a1i, c1kr, c1ki;
    {
        int i0 = d * DS + lane, i1 = i0 + 32;
        #pragma unroll
        for (int s = 0; s < 2; ++s) {
            int ii = s ? i1 : i0;
            float ar_ = Are[ii], ai_ = Aim[ii];
            float xr = dt * ar_, xi = dt * ai_;
            float mag = expf(xr);
            float cs = cosf(xi), sn = sinf(xi);
            float A_r = mag * cs, A_i = mag * sn;
            float em = expm1f(xr);
            float er = fmaf(em, cs, cs - 1.f);
            float ei = A_i;
            float inv = 1.f / fmaf(ar_, ar_, ai_ * ai_);
            float qr = fmaf(er, ar_, ei * ai_) * inv;
            float qi = fmaf(ei, ar_, -er * ai_) * inv;
            float cr = Cre[ii], ci = Cim[ii];
            float kr = 2.f * fmaf(cr, qr, -ci * qi);
            float ki = 2.f * fmaf(cr, qi, ci * qr);
            if (s == 0) { a0r = A_r; a0i = A_i; c0kr = kr; c0ki = ki; }
            else        { a1r = A_r; a1i = A_i; c1kr = kr; c1ki = ki; }
        }
    }
    ull ar2  = pk2(a0r, a1r);
    ull ai2  = pk2(a0i, a1i);
    ull nai2 = pk2(-a0i, -a1i);
    ull cr2  = pk2(c0kr, c1kr);
    ull nci2 = pk2(-c0ki, -c1ki);
    ull sr2 = 0ull, si2 = 0ull;
    float Dd = Dv[d];
    const float* u = g_h + ((size_t)b * DM + d) * LTP;
    int dp = threadIdx.x & 15, lrel = threadIdx.x >> 4;
    const int idx = lane & 15, part = lane >> 4;
    const float* rp = sp + idx * 68 + part * 32;

    for (int c4 = 0; c4 < 16; ++c4) {
        for (int cc = 0; cc < 4; ++cc) {
            int l0 = c4 * 128 + cc * 32;
            float rv = u[l0 + lane];
            rv = fmaf(rv - mean, scl, bet);
            #pragma unroll 1
            for (int sub = 0; sub < 2; ++sub) {
                #pragma unroll
                for (int j = 0; j < 16; ++j) {
                    float uv = __shfl_sync(0xffffffffu, rv, sub * 16 + j);
                    ull uv2 = pk2(uv, uv);
                    ull t   = f2fma(nai2, si2, uv2);
                    ull nsr = f2fma(ar2, sr2, t);
                    ull nsi = f2fma(ai2, sr2, f2mul(ar2, si2));
                    sr2 = nsr; si2 = nsi;
                    ull pr = f2fma(cr2, sr2, f2mul(nci2, si2));
                    *(ull*)&sp[j * 68 + 2 * lane] = pr;   // packed pair, STS.64
                }
                __syncwarp();
                ull a0 = 0ull, a1 = 0ull, a2 = 0ull, a3 = 0ull;
                #pragma unroll
                for (int m = 0; m < 4; ++m) {
                    ulonglong2 q  = *(const ulonglong2*)(rp + 8 * m);
                    ulonglong2 q2 = *(const ulonglong2*)(rp + 8 * m + 4);
                    a0 = f2add(a0, q.x);  a1 = f2add(a1, q.y);
                    a2 = f2add(a2, q2.x); a3 = f2add(a3, q2.y);
                }
                ull at = f2add(f2add(a0, a1), f2add(a2, a3));
                float px, py; up2(at, px, py);
                float p = px + py;
                p += __shfl_xor_sync(0xffffffffu, p, 16);
                float uvo = __shfl_sync(0xffffffffu, rv, sub * 16 + idx);
                if (part == 0)
                    stage[warp * 129 + cc * 32 + sub * 16 + idx] =
                        gelu_tanh(fmaf(Dd, uvo, p));
                __syncwarp();
            }
        }
        __syncthreads();
        #pragma unroll
        for (int p = 0; p < 2; ++p) {
            int l = lrel + p * 64;
            float v0 = stage[(2 * dp) * 129 + l];
            float v1 = stage[(2 * dp + 1) * 129 + l];
            u32 lo0, lo1;
            u32 h0 = bfsplit(v0, lo0);
            u32 h1 = bfsplit(v1, lo1);
            size_t row = ((size_t)b * LTT + c4 * 128 + l) * 128 + (dbase >> 1) + dp;
            g_yh[row] = h0 | (h1 << 16);
            g_yl[row] = lo0 | (lo1 << 16);
        }
        __syncthreads();
    }
    // tail: l = 2048..2054 (scalar path)
    {
        float rv = 0.f;
        if (lane < 7) rv = fmaf(u[2048 + lane] - mean, scl, bet);
        #pragma unroll
        for (int j = 0; j < 7; ++j) {
            float uv = __shfl_sync(0xffffffffu, rv, j);
            ull uv2 = pk2(uv, uv);
            ull t   = f2fma(nai2, si2, uv2);
            ull nsr = f2fma(ar2, sr2, t);
            ull nsi = f2fma(ai2, sr2, f2mul(ar2, si2));
            sr2 = nsr; si2 = nsi;
            ull pr = f2fma(cr2, sr2, f2mul(nci2, si2));
            float px, py; up2(pr, px, py);
            sp[j * 68 + lane] = px + py;
        }
        __syncwarp();
        if (lane < 7) {
            float q0 = 0.f, q1 = 0.f, q2 = 0.f, q3 = 0.f;
            #pragma unroll
            for (int k4 = 0; k4 < 32; k4 += 4) {
                float4 q = *(const float4*)&sp[lane * 68 + k4];
                q0 += q.x; q1 += q.y; q2 += q.z; q3 += q.w;
            }
            float cs = (q0 + q1) + (q2 + q3);
            stage[warp * 129 + lane] = gelu_tanh(fmaf(Dd, rv, cs));
        }
        __syncthreads();
        if (lrel < 7) {
            float v0 = stage[(2 * dp) * 129 + lrel];
            float v1 = stage[(2 * dp + 1) * 129 + lrel];
            u32 lo0, lo1;
            u32 h0 = bfsplit(v0, lo0);
            u32 h1 = bfsplit(v1, lo1);
            size_t row = ((size_t)b * LTT + 2048 + lrel) * 128 + (dbase >> 1) + dp;
            g_yh[row] = h0 | (h1 << 16);
            g_yl[row] = lo0 | (lo1 << 16);
        }
        // zero padded rows 2055..2111 (this block's 16 d-pair columns)
        if (threadIdx.x < 912) {
            int l = 2055 + threadIdx.x / 16;
            int dp2 = threadIdx.x & 15;
            size_t row = ((size_t)b * LTT + l) * 128 + (dbase >> 1) + dp2;
            g_yh[row] = 0u;
            g_yl[row] = 0u;
        }
    }
}

// ---- out-proj GEMM: split-bf16 HMMA (R6 mainloop) + parallel coalesced epilogue ----
extern "C" __global__ void __launch_bounds__(256) k_gemm(
        const float* __restrict__ ob, const float* __restrict__ pg,
        const float* __restrict__ pb, int apply_bn, int layer) {
    extern __shared__ u32 gsm[];
    // Ah: [0,4608)  Al: [4608,9216)  Bh: [9216,11520)  Bl: [11520,13824)   (u32 idx)
    const int bb = blockIdx.z, et = blockIdx.y, lt = blockIdx.x;
    const int e0 = et * 64, l0 = lt * 64;
    const int tid = threadIdx.x;
    const int wid = tid >> 5, lane = tid & 31;
    const int h = wid >> 2, wq = wid & 3;
    const int g = lane >> 2, t = lane & 3;
    const u32* Wh = g_wh[layer];
    const u32* Wl = g_wl[layer];
    float acc[4][2][4];
    #pragma unroll
    for (int mf = 0; mf < 4; ++mf)
        #pragma unroll
        for (int nf = 0; nf < 2; ++nf)
            #pragma unroll
            for (int r = 0; r < 4; ++r) acc[mf][nf][r] = 0.f;

    const int r_all = tid >> 3, j4 = (tid & 7) * 4;
    for (int kc = 0; kc < 4; ++kc) {
        const int kb2 = kc * 32;
        __syncthreads();
        #pragma unroll
        for (int p = 0; p < 4; ++p) {
            int row = p * 32 + r_all;      // 0..127
            int hh = row >> 6, r = row & 63;
            int eg = e0 + (hh ? 256 : 0) + r;
            *(uint4*)&gsm[(hh * 64 + r) * 36 + j4] =
                *(const uint4*)&Wh[(size_t)eg * 128 + kb2 + j4];
            *(uint4*)&gsm[4608 + (hh * 64 + r) * 36 + j4] =
                *(const uint4*)&Wl[(size_t)eg * 128 + kb2 + j4];
        }
        #pragma unroll
        for (int p = 0; p < 2; ++p) {
            int lrow = p * 32 + r_all;     // 0..63
            size_t yrow = ((size_t)bb * LTT + l0 + lrow) * 128 + kb2 + j4;
            *(uint4*)&gsm[9216 + lrow * 36 + j4] = *(const uint4*)&g_yh[yrow];
            *(uint4*)&gsm[11520 + lrow * 36 + j4] = *(const uint4*)&g_yl[yrow];
        }
        __syncthreads();
        const u32* A_h = gsm + h * 2304;
        const u32* A_l = gsm + 4608 + h * 2304;
        #pragma unroll
        for (int ks = 0; ks < 4; ++ks) {
            u32 ah[4][4], al[4][4], bh[2][2], bl[2][2];
            #pragma unroll
            for (int mf = 0; mf < 4; ++mf) {
                int rb = (16 * mf + g) * 36 + ks * 8 + t;
                ah[mf][0] = A_h[rb];       ah[mf][1] = A_h[rb + 288];
                ah[mf][2] = A_h[rb + 4];   ah[mf][3] = A_h[rb + 292];
                al[mf][0] = A_l[rb];       al[mf][1] = A_l[rb + 288];
                al[mf][2] = A_l[rb + 4];   al[mf][3] = A_l[rb + 292];
            }
            #pragma unroll
            for (int nf = 0; nf < 2; ++nf) {
                int nr = (wq * 16 + nf * 8 + g) * 36 + ks * 8 + t;
                bh[nf][0] = gsm[9216 + nr];  bh[nf][1] = gsm[9216 + nr + 4];
                bl[nf][0] = gsm[11520 + nr]; bl[nf][1] = gsm[11520 + nr + 4];
            }
            #pragma unroll
            for (int mf = 0; mf < 4; ++mf)
                #pragma unroll
                for (int nf = 0; nf < 2; ++nf) {
                    mma16816(acc[mf][nf], ah[mf], bh[nf]);
                    mma16816(acc[mf][nf], ah[mf], bl[nf]);
                    mma16816(acc[mf][nf], al[mf], bh[nf]);
                }
        }
    }
    __syncthreads();
    float* zb1 = (float*)gsm;               // [64][66]
    float* zb2 = (float*)(gsm + 4224);      // [64][66]
    float* zb = h ? zb2 : zb1;
    #pragma unroll
    for (int mf = 0; mf < 4; ++mf)
        #pragma unroll
        for (int nf = 0; nf < 2; ++nf) {
            int lc = wq * 16 + nf * 8 + 2 * t;
            zb[(16 * mf + g) * 66 + lc]     = acc[mf][nf][0];
            zb[(16 * mf + g) * 66 + lc + 1] = acc[mf][nf][1];
            zb[(16 * mf + g + 8) * 66 + lc]     = acc[mf][nf][2];
            zb[(16 * mf + g + 8) * 66 + lc + 1] = acc[mf][nf][3];
        }
    __syncthreads();
    {
        const int dd = tid >> 2, seg = tid & 3;
        const int d = e0 + dd;
        const int lbase = l0 + seg * 16;
        float bz1 = ob[d], bz2 = ob[DM + d];
        float mn = 0.f, sc = 1.f, bt = 0.f;
        if (apply_bn) { mn = g_mean[d]; sc = g_rstd[d] * pg[d]; bt = pb[d]; }
        float* hrow = g_h + ((size_t)bb * DM + d) * LTP;
        const float* z1r = zb1 + dd * 66 + seg * 16;
        const float* z2r = zb2 + dd * 66 + seg * 16;
        float s = 0.f, s2 = 0.f;
        #pragma unroll
        for (int i = 0; i < 16; i += 4) {
            int lg = lbase + i;
            if (lg + 3 < LT) {
                float4 hv = *(const float4*)&hrow[lg];
                float hn0, hn1, hn2, hn3;
                {
                    float z1 = z1r[i] + bz1,     z2 = z2r[i] + bz2;
                    hn0 = fmaf(hv.x - mn, sc, bt) + z1 * sigm(z2);
                }
                {
                    float z1 = z1r[i + 1] + bz1, z2 = z2r[i + 1] + bz2;
                    hn1 = fmaf(hv.y - mn, sc, bt) + z1 * sigm(z2);
                }
                {
                    float z1 = z1r[i + 2] + bz1, z2 = z2r[i + 2] + bz2;
                    hn2 = fmaf(hv.z - mn, sc, bt) + z1 * sigm(z2);
                }
                {
                    float z1 = z1r[i + 3] + bz1, z2 = z2r[i + 3] + bz2;
                    hn3 = fmaf(hv.w - mn, sc, bt) + z1 * sigm(z2);
                }
                *(float4*)&hrow[lg] = make_float4(hn0, hn1, hn2, hn3);
                s += (hn0 + hn1) + (hn2 + hn3);
                s2 = fmaf(hn0, hn0, s2); s2 = fmaf(hn1, hn1, s2);
                s2 = fmaf(hn2, hn2, s2); s2 = fmaf(hn3, hn3, s2);
            } else {
                #pragma unroll
                for (int k = 0; k < 4; ++k) {
                    int l = lg + k;
                    if (l < LT) {
                        float z1 = z1r[i + k] + bz1, z2 = z2r[i + k] + bz2;
                        float hn = fmaf(hrow[l] - mn, sc, bt) + z1 * sigm(z2);
                        hrow[l] = hn;
                        s += hn; s2 = fmaf(hn, hn, s2);
                    }
                }
            }
        }
        s  += __shfl_xor_sync(0xffffffffu, s, 1);
        s  += __shfl_xor_sync(0xffffffffu, s, 2);
        s2 += __shfl_xor_sync(0xffffffffu, s2, 1);
        s2 += __shfl_xor_sync(0xffffffffu, s2, 2);
        if (seg == 0) {
            int slot = lt * 32 + bb;
            g_bnp0[d * NT + slot] = s;
            g_bnp1[d * NT + slot] = s2;
        }
    }
}

// ---------------- BN finalize ----------------
__global__ void k_bnfin() {
    int d = blockIdx.x, tid = threadIdx.x;   // 256 threads
    float s = 0.f, s2 = 0.f;
    for (int i = tid; i < NT; i += 256) {
        s  += g_bnp0[d * NT + i];
        s2 += g_bnp1[d * NT + i];
    }
    __shared__ float sh1[256], sh2[256];
    sh1[tid] = s; sh2[tid] = s2;
    __syncthreads();
    for (int o = 128; o; o >>= 1) {
        if (tid < o) { sh1[tid] += sh1[tid + o]; sh2[tid] += sh2[tid + o]; }
        __syncthreads();
    }
    if (tid == 0) {
        float n = (float)(BB * LT);
        float mean = sh1[0] / n;
        float var = sh2[0] / n - mean * mean;
        g_mean[d] = mean;
        g_rstd[d] = rsqrtf(var + 1e-5f);
    }
}

// ---------------- head (applies final BN lazily) ----------------
__global__ void k_head(const float* __restrict__ W1, const float* __restrict__ b1,
                       const float* __restrict__ W2, const float* __restrict__ b2,
                       const float* __restrict__ pg, const float* __restrict__ pb,
                       float* __restrict__ out) {
    int i = blockIdx.x, b = blockIdx.y, tid = threadIdx.x;  // 128 threads
    int l = (LL - 1) + i;
    float acc = b1[tid];
    const float* Hb = g_h + (size_t)b * DM * LTP + l;
    #pragma unroll 4
    for (int d = 0; d < DM; ++d) {
        float v = fmaf(Hb[(size_t)d * LTP] - g_mean[d], g_rstd[d] * pg[d], pb[d]);
        acc = fmaf(v, W1[d * 128 + tid], acc);
    }
    float sv = acc * sigm(acc);
    __shared__ float sh[128];
    sh[tid] = sv * W2[tid];
    __syncthreads();
    for (int o = 64; o; o >>= 1) {
        if (tid < o) sh[tid] += sh[tid + o];
        __syncthreads();
    }
    if (tid == 0) out[b * HH + i] = sh[0] + b2[0];
}

// ---------------- launch ----------------
extern "C" void kernel_launch(void* const* d_in, const int* in_sizes, int n_in,
                              void* d_out, int out_size) {
    const float* x_past   = (const float*)d_in[0];
    const float* noisy    = (const float*)d_in[1];
    const float* t        = (const float*)d_in[2];
    const float* x_future = (const float*)d_in[3];
    const float* stat     = (const float*)d_in[4];
    const float* freqs    = (const float*)d_in[5];
    const float* phases   = (const float*)d_in[6];
    const float* in_W     = (const float*)d_in[7];
    const float* in_b     = (const float*)d_in[8];
    const float* tm_W1    = (const float*)d_in[9];
    const float* tm_b1    = (const float*)d_in[10];
    const float* tm_W2    = (const float*)d_in[11];
    const float* tm_b2    = (const float*)d_in[12];
    const float* log_dt   = (const float*)d_in[13];
    const float* A_re     = (const float*)d_in[14];
    const float* A_im     = (const float*)d_in[15];
    const float* C_re     = (const float*)d_in[16];
    const float* C_im     = (const float*)d_in[17];
    const float* Dv       = (const float*)d_in[18];
    const float* out_W    = (const float*)d_in[19];
    const float* out_b    = (const float*)d_in[20];
    const float* bn_g     = (const float*)d_in[21];
    const float* bn_b     = (const float*)d_in[22];
    const float* hW1      = (const float*)d_in[23];
    const float* hb1      = (const float*)d_in[24];
    const float* hW2      = (const float*)d_in[25];
    const float* hb2      = (const float*)d_in[26];
    float* out = (float*)d_out;

    cudaFuncSetAttribute(k_scan, cudaFuncAttributeMaxDynamicSharedMemorySize, SCAN_SMEM);
    cudaFuncSetAttribute(k_gemm, cudaFuncAttributeMaxDynamicSharedMemorySize, GEMM_SMEM);

    k_timemlp<<<BB, 256>>>(t, freqs, phases, tm_W1, tm_b1, tm_W2, tm_b2);
    k_wprep<<<1024, 256>>>(out_W);
    k_inproj<<<dim3(65, DM / 8, BB), 256>>>(x_past, noisy, x_future, stat, in_W, in_b);

    for (int i = 0; i < NLAYERS; ++i) {
        const float* pg = (i == 0) ? bn_g : bn_g + (i - 1) * DM;
        const float* pb = (i == 0) ? bn_b : bn_b + (i - 1) * DM;
        k_scan<<<256, 1024, SCAN_SMEM>>>(log_dt + i * DM,
                                         A_re + (size_t)i * DM * DS, A_im + (size_t)i * DM * DS,
                                         C_re + (size_t)i * DM * DS, C_im + (size_t)i * DM * DS,
                                         Dv + i * DM, pg, pb, i > 0);
        k_gemm<<<dim3(33, 4, BB), 256, GEMM_SMEM>>>(out_b + i * 2 * DM, pg, pb, i > 0, i);
        k_bnfin<<<DM, 256>>>();
    }
    k_head<<<dim3(HH, BB), 128>>>(hW1, hb1, hW2, hb2, bn_g + 3 * DM, bn_b + 3 * DM, out);
}

// round 16
// speedup vs baseline: 1.1356x; 1.1356x over previous
#include <cuda_runtime.h>
#include <cuda_bf16.h>
#include <math.h>

#define BB 32
#define LL 2048
#define HH 8
#define DMET 16
#define SDIM 27
#define DM 256
#define NLAYERS 4
#define DS 64
#define TE 256
#define LT 2055          // LL + HH - 1
#define LTP 2056         // padded row stride for g_h
#define LTT 2112         // 33*64 padded yT rows
#define FIN 44
#define NT 1056          // 33 l-tiles * 32 batches

typedef unsigned long long ull;
typedef unsigned int u32;

// ---------------- scratch (device globals; no allocation) ----------------
__device__ float g_h[(size_t)BB * DM * LTP];        // activations (pre-BN) [b][d][l]
__device__ u32 g_yh[(size_t)BB * LTT * 128];        // scan out, bf16-hi, [b][l][d/2] packed
__device__ u32 g_yl[(size_t)BB * LTT * 128];        // bf16-lo plane
__device__ u32 g_wh[NLAYERS][512 * 128];            // W^T split [layer][e][d/2] packed
__device__ u32 g_wl[NLAYERS][512 * 128];
__device__ float g_tb[BB * DM];
__device__ float g_mean[DM], g_rstd[DM];
__device__ float g_bnp0[DM * NT], g_bnp1[DM * NT];

#define SCAN_SMEM (163968)   // 32*1152 f32 (sp) + 32*129 f32 (stage)
#define GEMM_SMEM (55296)    // 13824 u32

// ---------------- f32x2 packed math ----------------
__device__ __forceinline__ ull pk2(float a, float b) {
    ull r; asm("mov.b64 %0,{%1,%2};" : "=l"(r) : "f"(a), "f"(b)); return r;
}
__device__ __forceinline__ void up2(ull v, float& a, float& b) {
    asm("mov.b64 {%0,%1},%2;" : "=f"(a), "=f"(b) : "l"(v));
}
__device__ __forceinline__ ull f2fma(ull a, ull b, ull c) {
    ull d; asm("fma.rn.f32x2 %0,%1,%2,%3;" : "=l"(d) : "l"(a), "l"(b), "l"(c)); return d;
}
__device__ __forceinline__ ull f2mul(ull a, ull b) {
    ull d; asm("mul.rn.f32x2 %0,%1,%2;" : "=l"(d) : "l"(a), "l"(b)); return d;
}

// ---------------- helpers ----------------
__device__ __forceinline__ float sigm(float x) { return 1.f / (1.f + __expf(-x)); }
__device__ __forceinline__ float gelu_tanh(float v) {
    float v3 = v * v * v;
    float w = 1.5957691216057308f * fmaf(0.044715f, v3, v);
    return v * sigm(w);
}
__device__ __forceinline__ u32 bfsplit(float x, u32& lo) {
    __nv_bfloat16 h = __float2bfloat16(x);
    float r = x - __bfloat162float(h);
    __nv_bfloat16 l = __float2bfloat16(r);
    lo = (u32)__bfloat16_as_ushort(l);
    return (u32)__bfloat16_as_ushort(h);
}
__device__ __forceinline__ void mma16816(float* c, const u32* a, const u32* b) {
    asm volatile(
        "mma.sync.aligned.m16n8k16.row.col.f32.bf16.bf16.f32 "
        "{%0,%1,%2,%3},{%4,%5,%6,%7},{%8,%9},{%0,%1,%2,%3};"
        : "+f"(c[0]), "+f"(c[1]), "+f"(c[2]), "+f"(c[3])
        : "r"(a[0]), "r"(a[1]), "r"(a[2]), "r"(a[3]), "r"(b[0]), "r"(b[1]));
}

// ---------------- time MLP ----------------
__global__ void k_timemlp(const float* __restrict__ t, const float* __restrict__ freqs,
                          const float* __restrict__ phases,
                          const float* __restrict__ W1, const float* __restrict__ b1,
                          const float* __restrict__ W2, const float* __restrict__ b2) {
    int b = blockIdx.x, tid = threadIdx.x;
    __shared__ float tf[TE];
    __shared__ float hid[2 * TE];
    float tv = t[b];
    tf[tid] = cosf(fmaf(tv, freqs[tid], phases[tid])) * 1.41421356237309515f;
    __syncthreads();
    for (int j = tid; j < 2 * TE; j += 256) {
        float acc = b1[j];
        #pragma unroll 8
        for (int k = 0; k < TE; ++k) acc = fmaf(tf[k], W1[k * 512 + j], acc);
        hid[j] = acc * sigm(acc);
    }
    __syncthreads();
    float acc = b2[tid];
    #pragma unroll 8
    for (int k = 0; k < 2 * TE; ++k) acc = fmaf(hid[k], W2[k * 256 + tid], acc);
    g_tb[b * DM + tid] = acc;
}

// ---------------- input projection ----------------
__global__ void k_inproj(const float* __restrict__ xp, const float* __restrict__ noisy,
                         const float* __restrict__ xf, const float* __restrict__ sa,
                         const float* __restrict__ inW, const float* __restrict__ inb) {
    int b = blockIdx.z, dt = blockIdx.y, ltile = blockIdx.x;
    int tid = threadIdx.x;
    int ll = tid & 31, dl = tid >> 5;
    int l0 = ltile * 32, d0 = dt * 8;
    __shared__ float sf[32][45];
    __shared__ float sw[FIN][8];
    for (int i = tid; i < 32 * FIN; i += 256) {
        int li = i / FIN, f = i % FIN;
        int l = l0 + li;
        float v = 0.f;
        if (l < LT) {
            if (f < DMET)
                v = (l < LL) ? xp[((size_t)b * LL + l) * DMET + f]
                             : xf[((size_t)b * (HH - 1) + (l - LL)) * DMET + f];
            else if (f == DMET)
                v = (l >= LL - 1) ? noisy[b * HH + (l - (LL - 1))] : 0.f;
            else
                v = sa[b * SDIM + (f - DMET - 1)];
        }
        sf[li][f] = v;
    }
    for (int i = tid; i < FIN * 8; i += 256) {
        int f = i >> 3, c = i & 7;
        sw[f][c] = inW[f * DM + d0 + c];
    }
    __syncthreads();
    int l = l0 + ll, d = d0 + dl;
    float acc = inb[d];
    #pragma unroll
    for (int f = 0; f < FIN; ++f) acc = fmaf(sf[ll][f], sw[f][dl], acc);
    if (l >= LL - 1) acc += g_tb[b * DM + d];
    if (l < LT) g_h[((size_t)b * DM + d) * LTP + l] = acc;
}

// ---------------- weight transpose + bf16 split (ALL layers, one launch) -----------
__global__ void k_wprep(const float* __restrict__ W) {
    int idx = blockIdx.x * 256 + threadIdx.x;   // 0..262143
    int layer = idx >> 16;
    int r = idx & 65535;
    int e = r & 511, kp = r >> 9;               // kp 0..127
    const float* Wl = W + (size_t)layer * DM * 2 * DM;
    float x0 = Wl[(2 * kp) * 512 + e];
    float x1 = Wl[(2 * kp + 1) * 512 + e];
    u32 lo0, lo1;
    u32 h0 = bfsplit(x0, lo0);
    u32 h1 = bfsplit(x1, lo1);
    g_wh[layer][e * 128 + kp] = h0 | (h1 << 16);
    g_wl[layer][e * 128 + kp] = lo0 | (lo1 << 16);
}

// ---------------- one-time zero-pad of yT rows 2055..2111 (all b, all d) ----------
__global__ void k_zpad() {
    int idx = blockIdx.x * 256 + threadIdx.x;   // BB * 57 * 128 = 233472
    int b = idx / (57 * 128);
    int r = idx % (57 * 128);
    int l = 2055 + r / 128, c = r % 128;
    size_t row = ((size_t)b * LTT + l) * 128 + c;
    g_yh[row] = 0u;
    g_yl[row] = 0u;
}

// ---- SSM scan: 1024 thr (32 warps = 32 d), inline disc, f32x2, transposed split out
extern "C" __global__ void __launch_bounds__(1024) k_scan(
        const float* __restrict__ log_dt, const float* __restrict__ Are,
        const float* __restrict__ Aim, const float* __restrict__ Cre,
        const float* __restrict__ Cim, const float* __restrict__ Dv,
        const float* __restrict__ pg, const float* __restrict__ pb, int apply_bn) {
    extern __shared__ float dyn[];
    int warp = threadIdx.x >> 5, lane = threadIdx.x & 31;
    float* sp = dyn + warp * 1152;          // [32 step][36] per warp
    float* stage = dyn + 32 * 1152;         // [32 d][129]
    int b = blockIdx.x >> 3, dbase = (blockIdx.x & 7) * 32;
    int d = dbase + warp;
    float mean = 0.f, scl = 1.f, bet = 0.f;
    if (apply_bn) { mean = g_mean[d]; scl = g_rstd[d] * pg[d]; bet = pb[d]; }
    float dt = __expf(log_dt[d]);
    float a0r, a0i, c0kr, c0ki, a1r, a1i, c1kr, c1ki;
    {
        int i0 = d * DS + lane, i1 = i0 + 32;
        #pragma unroll
        for (int s = 0; s < 2; ++s) {
            int ii = s ? i1 : i0;
            float ar_ = Are[ii], ai_ = Aim[ii];
            float xr = dt * ar_, xi = dt * ai_;
            float mag = expf(xr);
            float cs = cosf(xi), sn = sinf(xi);
            float A_r = mag * cs, A_i = mag * sn;
            float em = expm1f(xr);
            float er = fmaf(em, cs, cs - 1.f);
            float ei = A_i;
            float inv = 1.f / fmaf(ar_, ar_, ai_ * ai_);
            float qr = fmaf(er, ar_, ei * ai_) * inv;
            float qi = fmaf(ei, ar_, -er * ai_) * inv;
            float cr = Cre[ii], ci = Cim[ii];
            float kr = 2.f * fmaf(cr, qr, -ci * qi);
            float ki = 2.f * fmaf(cr, qi, ci * qr);
            if (s == 0) { a0r = A_r; a0i = A_i; c0kr = kr; c0ki = ki; }
            else        { a1r = A_r; a1i = A_i; c1kr = kr; c1ki = ki; }
        }
    }
    ull ar2  = pk2(a0r, a1r);
    ull ai2  = pk2(a0i, a1i);
    ull nai2 = pk2(-a0i, -a1i);
    ull cr2  = pk2(c0kr, c1kr);
    ull nci2 = pk2(-c0ki, -c1ki);
    ull sr2 = 0ull, si2 = 0ull;
    float Dd = Dv[d];
    const float* u = g_h + ((size_t)b * DM + d) * LTP;
    int dp = threadIdx.x & 15, lrel = threadIdx.x >> 4;

    for (int c4 = 0; c4 < 16; ++c4) {
        for (int cc = 0; cc < 4; ++cc) {
            int l0 = c4 * 128 + cc * 32;
            float rv = u[l0 + lane];
            rv = fmaf(rv - mean, scl, bet);
            #pragma unroll
            for (int j = 0; j < 32; ++j) {
                float uv = __shfl_sync(0xffffffffu, rv, j);
                ull uv2 = pk2(uv, uv);
                ull t   = f2fma(nai2, si2, uv2);
                ull nsr = f2fma(ar2, sr2, t);
                ull nsi = f2fma(ai2, sr2, f2mul(ar2, si2));
                sr2 = nsr; si2 = nsi;
                ull pr = f2fma(cr2, sr2, f2mul(nci2, si2));
                float px, py; up2(pr, px, py);
                sp[j * 36 + lane] = px + py;
            }
            __syncwarp();
            float q0 = 0.f, q1 = 0.f, q2 = 0.f, q3 = 0.f;
            #pragma unroll
            for (int k4 = 0; k4 < 32; k4 += 4) {
                float4 q = *(const float4*)&sp[lane * 36 + k4];
                q0 += q.x; q1 += q.y; q2 += q.z; q3 += q.w;
            }
            float cs = (q0 + q1) + (q2 + q3);
            stage[warp * 129 + cc * 32 + lane] = gelu_tanh(fmaf(Dd, rv, cs));
            __syncwarp();
        }
        __syncthreads();
        #pragma unroll
        for (int p = 0; p < 2; ++p) {
            int l = lrel + p * 64;
            float v0 = stage[(2 * dp) * 129 + l];
            float v1 = stage[(2 * dp + 1) * 129 + l];
            u32 lo0, lo1;
            u32 h0 = bfsplit(v0, lo0);
            u32 h1 = bfsplit(v1, lo1);
            size_t row = ((size_t)b * LTT + c4 * 128 + l) * 128 + (dbase >> 1) + dp;
            g_yh[row] = h0 | (h1 << 16);
            g_yl[row] = lo0 | (lo1 << 16);
        }
        __syncthreads();
    }
    // tail: l = 2048..2054
    {
        float rv = 0.f;
        if (lane < 7) rv = fmaf(u[2048 + lane] - mean, scl, bet);
        #pragma unroll
        for (int j = 0; j < 7; ++j) {
            float uv = __shfl_sync(0xffffffffu, rv, j);
            ull uv2 = pk2(uv, uv);
            ull t   = f2fma(nai2, si2, uv2);
            ull nsr = f2fma(ar2, sr2, t);
            ull nsi = f2fma(ai2, sr2, f2mul(ar2, si2));
            sr2 = nsr; si2 = nsi;
            ull pr = f2fma(cr2, sr2, f2mul(nci2, si2));
            float px, py; up2(pr, px, py);
            sp[j * 36 + lane] = px + py;
        }
        __syncwarp();
        if (lane < 7) {
            float q0 = 0.f, q1 = 0.f, q2 = 0.f, q3 = 0.f;
            #pragma unroll
            for (int k4 = 0; k4 < 32; k4 += 4) {
                float4 q = *(const float4*)&sp[lane * 36 + k4];
                q0 += q.x; q1 += q.y; q2 += q.z; q3 += q.w;
            }
            float cs = (q0 + q1) + (q2 + q3);
            stage[warp * 129 + lane] = gelu_tanh(fmaf(Dd, rv, cs));
        }
        __syncthreads();
        if (lrel < 7) {
            float v0 = stage[(2 * dp) * 129 + lrel];
            float v1 = stage[(2 * dp + 1) * 129 + lrel];
            u32 lo0, lo1;
            u32 h0 = bfsplit(v0, lo0);
            u32 h1 = bfsplit(v1, lo1);
            size_t row = ((size_t)b * LTT + 2048 + lrel) * 128 + (dbase >> 1) + dp;
            g_yh[row] = h0 | (h1 << 16);
            g_yl[row] = lo0 | (lo1 << 16);
        }
    }
}

// ---- out-proj GEMM: split-bf16 HMMA (R6 mainloop) + parallel coalesced epilogue ----
extern "C" __global__ void __launch_bounds__(256) k_gemm(
        const float* __restrict__ ob, const float* __restrict__ pg,
        const float* __restrict__ pb, int apply_bn, int layer) {
    extern __shared__ u32 gsm[];
    // Ah: [0,4608)  Al: [4608,9216)  Bh: [9216,11520)  Bl: [11520,13824)   (u32 idx)
    const int bb = blockIdx.z, et = blockIdx.y, lt = blockIdx.x;
    const int e0 = et * 64, l0 = lt * 64;
    const int tid = threadIdx.x;
    const int wid = tid >> 5, lane = tid & 31;
    const int h = wid >> 2, wq = wid & 3;
    const int g = lane >> 2, t = lane & 3;
    const u32* Wh = g_wh[layer];
    const u32* Wl = g_wl[layer];
    float acc[4][2][4];
    #pragma unroll
    for (int mf = 0; mf < 4; ++mf)
        #pragma unroll
        for (int nf = 0; nf < 2; ++nf)
            #pragma unroll
            for (int r = 0; r < 4; ++r) acc[mf][nf][r] = 0.f;

    const int r_all = tid >> 3, j4 = (tid & 7) * 4;
    for (int kc = 0; kc < 4; ++kc) {
        const int kb2 = kc * 32;
        __syncthreads();
        #pragma unroll
        for (int p = 0; p < 4; ++p) {
            int row = p * 32 + r_all;      // 0..127
            int hh = row >> 6, r = row & 63;
            int eg = e0 + (hh ? 256 : 0) + r;
            *(uint4*)&gsm[(hh * 64 + r) * 36 + j4] =
                *(const uint4*)&Wh[(size_t)eg * 128 + kb2 + j4];
            *(uint4*)&gsm[4608 + (hh * 64 + r) * 36 + j4] =
                *(const uint4*)&Wl[(size_t)eg * 128 + kb2 + j4];
        }
        #pragma unroll
        for (int p = 0; p < 2; ++p) {
            int lrow = p * 32 + r_all;     // 0..63
            size_t yrow = ((size_t)bb * LTT + l0 + lrow) * 128 + kb2 + j4;
            *(uint4*)&gsm[9216 + lrow * 36 + j4] = *(const uint4*)&g_yh[yrow];
            *(uint4*)&gsm[11520 + lrow * 36 + j4] = *(const uint4*)&g_yl[yrow];
        }
        __syncthreads();
        const u32* A_h = gsm + h * 2304;
        const u32* A_l = gsm + 4608 + h * 2304;
        #pragma unroll
        for (int ks = 0; ks < 4; ++ks) {
            u32 ah[4][4], al[4][4], bh[2][2], bl[2][2];
            #pragma unroll
            for (int mf = 0; mf < 4; ++mf) {
                int rb = (16 * mf + g) * 36 + ks * 8 + t;
                ah[mf][0] = A_h[rb];       ah[mf][1] = A_h[rb + 288];
                ah[mf][2] = A_h[rb + 4];   ah[mf][3] = A_h[rb + 292];
                al[mf][0] = A_l[rb];       al[mf][1] = A_l[rb + 288];
                al[mf][2] = A_l[rb + 4];   al[mf][3] = A_l[rb + 292];
            }
            #pragma unroll
            for (int nf = 0; nf < 2; ++nf) {
                int nr = (wq * 16 + nf * 8 + g) * 36 + ks * 8 + t;
                bh[nf][0] = gsm[9216 + nr];  bh[nf][1] = gsm[9216 + nr + 4];
                bl[nf][0] = gsm[11520 + nr]; bl[nf][1] = gsm[11520 + nr + 4];
            }
            #pragma unroll
            for (int mf = 0; mf < 4; ++mf)
                #pragma unroll
                for (int nf = 0; nf < 2; ++nf) {
                    mma16816(acc[mf][nf], ah[mf], bh[nf]);
                    mma16816(acc[mf][nf], ah[mf], bl[nf]);
                    mma16816(acc[mf][nf], al[mf], bh[nf]);
                }
        }
    }
    __syncthreads();
    // dump both GLU halves: z1 (h==0 accs) -> zb1, z2 (h==1 accs) -> zb2
    float* zb1 = (float*)gsm;               // [64][66]
    float* zb2 = (float*)(gsm + 4224);      // [64][66]
    float* zb = h ? zb2 : zb1;
    #pragma unroll
    for (int mf = 0; mf < 4; ++mf)
        #pragma unroll
        for (int nf = 0; nf < 2; ++nf) {
            int lc = wq * 16 + nf * 8 + 2 * t;
            zb[(16 * mf + g) * 66 + lc]     = acc[mf][nf][0];
            zb[(16 * mf + g) * 66 + lc + 1] = acc[mf][nf][1];
            zb[(16 * mf + g + 8) * 66 + lc]     = acc[mf][nf][2];
            zb[(16 * mf + g + 8) * 66 + lc + 1] = acc[mf][nf][3];
        }
    __syncthreads();
    // coalesced fused epilogue: all 256 threads; thread = (row dd, 16-l segment)
    {
        const int dd = tid >> 2, seg = tid & 3;
        const int d = e0 + dd;
        const int lbase = l0 + seg * 16;
        float bz1 = ob[d], bz2 = ob[DM + d];
        float mn = 0.f, sc = 1.f, bt = 0.f;
        if (apply_bn) { mn = g_mean[d]; sc = g_rstd[d] * pg[d]; bt = pb[d]; }
        float* hrow = g_h + ((size_t)bb * DM + d) * LTP;
        const float* z1r = zb1 + dd * 66 + seg * 16;
        const float* z2r = zb2 + dd * 66 + seg * 16;
        float s = 0.f, s2 = 0.f;
        #pragma unroll
        for (int i = 0; i < 16; i += 4) {
            int lg = lbase + i;
            if (lg + 3 < LT) {
                float4 hv = *(const float4*)&hrow[lg];
                float hn0, hn1, hn2, hn3;
                {
                    float z1 = z1r[i] + bz1,     z2 = z2r[i] + bz2;
                    hn0 = fmaf(hv.x - mn, sc, bt) + z1 * sigm(z2);
                }
                {
                    float z1 = z1r[i + 1] + bz1, z2 = z2r[i + 1] + bz2;
                    hn1 = fmaf(hv.y - mn, sc, bt) + z1 * sigm(z2);
                }
                {
                    float z1 = z1r[i + 2] + bz1, z2 = z2r[i + 2] + bz2;
                    hn2 = fmaf(hv.z - mn, sc, bt) + z1 * sigm(z2);
                }
                {
                    float z1 = z1r[i + 3] + bz1, z2 = z2r[i + 3] + bz2;
                    hn3 = fmaf(hv.w - mn, sc, bt) + z1 * sigm(z2);
                }
                *(float4*)&hrow[lg] = make_float4(hn0, hn1, hn2, hn3);
                s += (hn0 + hn1) + (hn2 + hn3);
                s2 = fmaf(hn0, hn0, s2); s2 = fmaf(hn1, hn1, s2);
                s2 = fmaf(hn2, hn2, s2); s2 = fmaf(hn3, hn3, s2);
            } else {
                #pragma unroll
                for (int k = 0; k < 4; ++k) {
                    int l = lg + k;
                    if (l < LT) {
                        float z1 = z1r[i + k] + bz1, z2 = z2r[i + k] + bz2;
                        float hn = fmaf(hrow[l] - mn, sc, bt) + z1 * sigm(z2);
                        hrow[l] = hn;
                        s += hn; s2 = fmaf(hn, hn, s2);
                    }
                }
            }
        }
        s  += __shfl_xor_sync(0xffffffffu, s, 1);
        s  += __shfl_xor_sync(0xffffffffu, s, 2);
        s2 += __shfl_xor_sync(0xffffffffu, s2, 1);
        s2 += __shfl_xor_sync(0xffffffffu, s2, 2);
        if (seg == 0) {
            int slot = lt * 32 + bb;
            g_bnp0[d * NT + slot] = s;
            g_bnp1[d * NT + slot] = s2;
        }
    }
}

// ---------------- BN finalize ----------------
__global__ void k_bnfin() {
    int d = blockIdx.x, tid = threadIdx.x;   // 256 threads
    float s = 0.f, s2 = 0.f;
    for (int i = tid; i < NT; i += 256) {
        s  += g_bnp0[d * NT + i];
        s2 += g_bnp1[d * NT + i];
    }
    __shared__ float sh1[256], sh2[256];
    sh1[tid] = s; sh2[tid] = s2;
    __syncthreads();
    for (int o = 128; o; o >>= 1) {
        if (tid < o) { sh1[tid] += sh1[tid + o]; sh2[tid] += sh2[tid + o]; }
        __syncthreads();
    }
    if (tid == 0) {
        float n = (float)(BB * LT);
        float mean = sh1[0] / n;
        float var = sh2[0] / n - mean * mean;
        g_mean[d] = mean;
        g_rstd[d] = rsqrtf(var + 1e-5f);
    }
}

// ---------------- head (applies final BN lazily) ----------------
__global__ void k_head(const float* __restrict__ W1, const float* __restrict__ b1,
                       const float* __restrict__ W2, const float* __restrict__ b2,
                       const float* __restrict__ pg, const float* __restrict__ pb,
                       float* __restrict__ out) {
    int i = blockIdx.x, b = blockIdx.y, tid = threadIdx.x;  // 128 threads
    int l = (LL - 1) + i;
    float acc = b1[tid];
    const float* Hb = g_h + (size_t)b * DM * LTP + l;
    #pragma unroll 4
    for (int d = 0; d < DM; ++d) {
        float v = fmaf(Hb[(size_t)d * LTP] - g_mean[d], g_rstd[d] * pg[d], pb[d]);
        acc = fmaf(v, W1[d * 128 + tid], acc);
    }
    float sv = acc * sigm(acc);
    __shared__ float sh[128];
    sh[tid] = sv * W2[tid];
    __syncthreads();
    for (int o = 64; o; o >>= 1) {
        if (tid < o) sh[tid] += sh[tid + o];
        __syncthreads();
    }
    if (tid == 0) out[b * HH + i] = sh[0] + b2[0];
}

// ---------------- launch ----------------
extern "C" void kernel_launch(void* const* d_in, const int* in_sizes, int n_in,
                              void* d_out, int out_size) {
    const float* x_past   = (const float*)d_in[0];
    const float* noisy    = (const float*)d_in[1];
    const float* t        = (const float*)d_in[2];
    const float* x_future = (const float*)d_in[3];
    const float* stat     = (const float*)d_in[4];
    const float* freqs    = (const float*)d_in[5];
    const float* phases   = (const float*)d_in[6];
    const float* in_W     = (const float*)d_in[7];
    const float* in_b     = (const float*)d_in[8];
    const float* tm_W1    = (const float*)d_in[9];
    const float* tm_b1    = (const float*)d_in[10];
    const float* tm_W2    = (const float*)d_in[11];
    const float* tm_b2    = (const float*)d_in[12];
    const float* log_dt   = (const float*)d_in[13];
    const float* A_re     = (const float*)d_in[14];
    const float* A_im     = (const float*)d_in[15];
    const float* C_re     = (const float*)d_in[16];
    const float* C_im     = (const float*)d_in[17];
    const float* Dv       = (const float*)d_in[18];
    const float* out_W    = (const float*)d_in[19];
    const float* out_b    = (const float*)d_in[20];
    const float* bn_g     = (const float*)d_in[21];
    const float* bn_b     = (const float*)d_in[22];
    const float* hW1      = (const float*)d_in[23];
    const float* hb1      = (const float*)d_in[24];
    const float* hW2      = (const float*)d_in[25];
    const float* hb2      = (const float*)d_in[26];
    float* out = (float*)d_out;

    cudaFuncSetAttribute(k_scan, cudaFuncAttributeMaxDynamicSharedMemorySize, SCAN_SMEM);
    cudaFuncSetAttribute(k_gemm, cudaFuncAttributeMaxDynamicSharedMemorySize, GEMM_SMEM);

    k_timemlp<<<BB, 256>>>(t, freqs, phases, tm_W1, tm_b1, tm_W2, tm_b2);
    k_wprep<<<1024, 256>>>(out_W);
    k_zpad<<<912, 256>>>();
    k_inproj<<<dim3(65, DM / 8, BB), 256>>>(x_past, noisy, x_future, stat, in_W, in_b);

    for (int i = 0; i < NLAYERS; ++i) {
        const float* pg = (i == 0) ? bn_g : bn_g + (i - 1) * DM;
        const float* pb = (i == 0) ? bn_b : bn_b + (i - 1) * DM;
        k_scan<<<256, 1024, SCAN_SMEM>>>(log_dt + i * DM,
                                         A_re + (size_t)i * DM * DS, A_im + (size_t)i * DM * DS,
                                         C_re + (size_t)i * DM * DS, C_im + (size_t)i * DM * DS,
                                         Dv + i * DM, pg, pb, i > 0);
        k_gemm<<<dim3(33, 4, BB), 256, GEMM_SMEM>>>(out_b + i * 2 * DM, pg, pb, i > 0, i);
        k_bnfin<<<DM, 256>>>();
    }
    k_head<<<dim3(HH, BB), 128>>>(hW1, hb1, hW2, hb2, bn_g + 3 * DM, bn_b + 3 * DM, out);
}

// round 17
// speedup vs baseline: 1.2231x; 1.0771x over previous
#include <cuda_runtime.h>
#include <cuda_bf16.h>
#include <math.h>

#define BB 32
#define LL 2048
#define HH 8
#define DMET 16
#define SDIM 27
#define DM 256
#define NLAYERS 4
#define DS 64
#define TE 256
#define LT 2055          // LL + HH - 1
#define LTP 2056         // padded row stride for g_h
#define LTT 2112         // 33*64 padded yT rows
#define FIN 44
#define NT 1056          // 33 l-tiles * 32 batches

typedef unsigned long long ull;
typedef unsigned int u32;

// ---------------- scratch (device globals; no allocation) ----------------
__device__ float g_h[(size_t)BB * DM * LTP];        // activations (pre-BN) [b][d][l]
__device__ u32 g_yh[(size_t)BB * LTT * 128];        // scan out, bf16-hi, [b][l][d/2] packed
__device__ u32 g_yl[(size_t)BB * LTT * 128];        // bf16-lo plane
__device__ u32 g_wh[NLAYERS][512 * 128];            // W^T split [layer][e][d/2] packed
__device__ u32 g_wl[NLAYERS][512 * 128];
__device__ float g_tb[BB * DM];
__device__ float g_mean[DM], g_rstd[DM];
__device__ float g_bnp0[DM * NT], g_bnp1[DM * NT];

#define SCAN_SMEM (163968)   // 32*1152 f32 (sp) + 32*129 f32 (stage)
#define GEMM_SMEM (55296)    // 13824 u32

// ---------------- f32x2 packed math ----------------
__device__ __forceinline__ ull pk2(float a, float b) {
    ull r; asm("mov.b64 %0,{%1,%2};" : "=l"(r) : "f"(a), "f"(b)); return r;
}
__device__ __forceinline__ void up2(ull v, float& a, float& b) {
    asm("mov.b64 {%0,%1},%2;" : "=f"(a), "=f"(b) : "l"(v));
}
__device__ __forceinline__ ull f2fma(ull a, ull b, ull c) {
    ull d; asm("fma.rn.f32x2 %0,%1,%2,%3;" : "=l"(d) : "l"(a), "l"(b), "l"(c)); return d;
}
__device__ __forceinline__ ull f2mul(ull a, ull b) {
    ull d; asm("mul.rn.f32x2 %0,%1,%2;" : "=l"(d) : "l"(a), "l"(b)); return d;
}

// ---------------- helpers ----------------
__device__ __forceinline__ float sigm(float x) { return 1.f / (1.f + __expf(-x)); }
__device__ __forceinline__ float gelu_tanh(float v) {
    float v3 = v * v * v;
    float w = 1.5957691216057308f * fmaf(0.044715f, v3, v);
    return v * sigm(w);
}
__device__ __forceinline__ u32 bfsplit(float x, u32& lo) {
    __nv_bfloat16 h = __float2bfloat16(x);
    float r = x - __bfloat162float(h);
    __nv_bfloat16 l = __float2bfloat16(r);
    lo = (u32)__bfloat16_as_ushort(l);
    return (u32)__bfloat16_as_ushort(h);
}
__device__ __forceinline__ void mma16816(float* c, const u32* a, const u32* b) {
    asm volatile(
        "mma.sync.aligned.m16n8k16.row.col.f32.bf16.bf16.f32 "
        "{%0,%1,%2,%3},{%4,%5,%6,%7},{%8,%9},{%0,%1,%2,%3};"
        : "+f"(c[0]), "+f"(c[1]), "+f"(c[2]), "+f"(c[3])
        : "r"(a[0]), "r"(a[1]), "r"(a[2]), "r"(a[3]), "r"(b[0]), "r"(b[1]));
}

// ---------------- time MLP ----------------
__global__ void k_timemlp(const float* __restrict__ t, const float* __restrict__ freqs,
                          const float* __restrict__ phases,
                          const float* __restrict__ W1, const float* __restrict__ b1,
                          const float* __restrict__ W2, const float* __restrict__ b2) {
    int b = blockIdx.x, tid = threadIdx.x;
    __shared__ float tf[TE];
    __shared__ float hid[2 * TE];
    float tv = t[b];
    tf[tid] = cosf(fmaf(tv, freqs[tid], phases[tid])) * 1.41421356237309515f;
    __syncthreads();
    for (int j = tid; j < 2 * TE; j += 256) {
        float acc = b1[j];
        #pragma unroll 8
        for (int k = 0; k < TE; ++k) acc = fmaf(tf[k], W1[k * 512 + j], acc);
        hid[j] = acc * sigm(acc);
    }
    __syncthreads();
    float acc = b2[tid];
    #pragma unroll 8
    for (int k = 0; k < 2 * TE; ++k) acc = fmaf(hid[k], W2[k * 256 + tid], acc);
    g_tb[b * DM + tid] = acc;
}

// ---- input projection: 32l x 64d blocks, shift-only staging, reg-resident feats ----
__global__ void __launch_bounds__(256) k_inproj(
        const float* __restrict__ xp, const float* __restrict__ noisy,
        const float* __restrict__ xf, const float* __restrict__ sa,
        const float* __restrict__ inW, const float* __restrict__ inb) {
    int b = blockIdx.z, dt = blockIdx.y, ltile = blockIdx.x;
    int tid = threadIdx.x;
    int ll = tid & 31, wgrp = tid >> 5;        // 8 warps, each owns 8 d
    int l0 = ltile * 32, d0 = dt * 64;
    __shared__ float sf[32][45];
    __shared__ float sw[FIN][64];
    // stage features: padded 32x64 index space, shifts only
    #pragma unroll
    for (int it = 0; it < 8; ++it) {
        int i = tid + it * 256;
        int li = i >> 6, f = i & 63;
        if (f < FIN) {
            int l = l0 + li;
            float v = 0.f;
            if (l < LT) {
                if (f < DMET)
                    v = (l < LL) ? xp[((size_t)b * LL + l) * DMET + f]
                                 : xf[((size_t)b * (HH - 1) + (l - LL)) * DMET + f];
                else if (f == DMET)
                    v = (l >= LL - 1) ? noisy[b * HH + (l - (LL - 1))] : 0.f;
                else
                    v = sa[b * SDIM + (f - DMET - 1)];
            }
            sf[li][f] = v;
        }
    }
    // stage weights: 44 x 64, shifts only
    for (int i = tid; i < FIN * 64; i += 256) {
        int f = i >> 6, c = i & 63;
        sw[f][c] = inW[f * DM + d0 + c];
    }
    __syncthreads();
    // pull this thread's feature row into registers
    float fv[FIN];
    #pragma unroll
    for (int f = 0; f < FIN; ++f) fv[f] = sf[ll][f];
    int l = l0 + ll;
    bool wr = (l < LT);
    bool tb = (l >= LL - 1);
    #pragma unroll
    for (int j = 0; j < 8; ++j) {
        int dc = wgrp * 8 + j;
        int d = d0 + dc;
        float acc = inb[d];
        #pragma unroll
        for (int f = 0; f < FIN; ++f) acc = fmaf(fv[f], sw[f][dc], acc);
        if (tb) acc += g_tb[b * DM + d];
        if (wr) g_h[((size_t)b * DM + d) * LTP + l] = acc;
    }
}

// ---------------- weight transpose + bf16 split (ALL layers, one launch) -----------
__global__ void k_wprep(const float* __restrict__ W) {
    int idx = blockIdx.x * 256 + threadIdx.x;   // 0..262143
    int layer = idx >> 16;
    int r = idx & 65535;
    int e = r & 511, kp = r >> 9;               // kp 0..127
    const float* Wl = W + (size_t)layer * DM * 2 * DM;
    float x0 = Wl[(2 * kp) * 512 + e];
    float x1 = Wl[(2 * kp + 1) * 512 + e];
    u32 lo0, lo1;
    u32 h0 = bfsplit(x0, lo0);
    u32 h1 = bfsplit(x1, lo1);
    g_wh[layer][e * 128 + kp] = h0 | (h1 << 16);
    g_wl[layer][e * 128 + kp] = lo0 | (lo1 << 16);
}

// ---------------- one-time zero-pad of yT rows 2055..2111 (all b, all d) ----------
__global__ void k_zpad() {
    int idx = blockIdx.x * 256 + threadIdx.x;   // BB * 57 * 128 = 233472
    int b = idx / (57 * 128);
    int r = idx % (57 * 128);
    int l = 2055 + r / 128, c = r % 128;
    size_t row = ((size_t)b * LTT + l) * 128 + c;
    g_yh[row] = 0u;
    g_yl[row] = 0u;
}

// ---- SSM scan: 1024 thr (32 warps = 32 d), inline disc, f32x2, transposed split out
extern "C" __global__ void __launch_bounds__(1024) k_scan(
        const float* __restrict__ log_dt, const float* __restrict__ Are,
        const float* __restrict__ Aim, const float* __restrict__ Cre,
        const float* __restrict__ Cim, const float* __restrict__ Dv,
        const float* __restrict__ pg, const float* __restrict__ pb, int apply_bn) {
    extern __shared__ float dyn[];
    int warp = threadIdx.x >> 5, lane = threadIdx.x & 31;
    float* sp = dyn + warp * 1152;          // [32 step][36] per warp
    float* stage = dyn + 32 * 1152;         // [32 d][129]
    int b = blockIdx.x >> 3, dbase = (blockIdx.x & 7) * 32;
    int d = dbase + warp;
    float mean = 0.f, scl = 1.f, bet = 0.f;
    if (apply_bn) { mean = g_mean[d]; scl = g_rstd[d] * pg[d]; bet = pb[d]; }
    float dt = __expf(log_dt[d]);
    float a0r, a0i, c0kr, c0ki, a1r, a1i, c1kr, c1ki;
    {
        int i0 = d * DS + lane, i1 = i0 + 32;
        #pragma unroll
        for (int s = 0; s < 2; ++s) {
            int ii = s ? i1 : i0;
            float ar_ = Are[ii], ai_ = Aim[ii];
            float xr = dt * ar_, xi = dt * ai_;
            float mag = expf(xr);
            float cs = cosf(xi), sn = sinf(xi);
            float A_r = mag * cs, A_i = mag * sn;
            float em = expm1f(xr);
            float er = fmaf(em, cs, cs - 1.f);
            float ei = A_i;
            float inv = 1.f / fmaf(ar_, ar_, ai_ * ai_);
            float qr = fmaf(er, ar_, ei * ai_) * inv;
            float qi = fmaf(ei, ar_, -er * ai_) * inv;
            float cr = Cre[ii], ci = Cim[ii];
            float kr = 2.f * fmaf(cr, qr, -ci * qi);
            float ki = 2.f * fmaf(cr, qi, ci * qr);
            if (s == 0) { a0r = A_r; a0i = A_i; c0kr = kr; c0ki = ki; }
            else        { a1r = A_r; a1i = A_i; c1kr = kr; c1ki = ki; }
        }
    }
    ull ar2  = pk2(a0r, a1r);
    ull ai2  = pk2(a0i, a1i);
    ull nai2 = pk2(-a0i, -a1i);
    ull cr2  = pk2(c0kr, c1kr);
    ull nci2 = pk2(-c0ki, -c1ki);
    ull sr2 = 0ull, si2 = 0ull;
    float Dd = Dv[d];
    const float* u = g_h + ((size_t)b * DM + d) * LTP;
    int dp = threadIdx.x & 15, lrel = threadIdx.x >> 4;

    for (int c4 = 0; c4 < 16; ++c4) {
        for (int cc = 0; cc < 4; ++cc) {
            int l0 = c4 * 128 + cc * 32;
            float rv = u[l0 + lane];
            rv = fmaf(rv - mean, scl, bet);
            #pragma unroll
            for (int j = 0; j < 32; ++j) {
                float uv = __shfl_sync(0xffffffffu, rv, j);
                ull uv2 = pk2(uv, uv);
                ull t   = f2fma(nai2, si2, uv2);
                ull nsr = f2fma(ar2, sr2, t);
                ull nsi = f2fma(ai2, sr2, f2mul(ar2, si2));
                sr2 = nsr; si2 = nsi;
                ull pr = f2fma(cr2, sr2, f2mul(nci2, si2));
                float px, py; up2(pr, px, py);
                sp[j * 36 + lane] = px + py;
            }
            __syncwarp();
            float q0 = 0.f, q1 = 0.f, q2 = 0.f, q3 = 0.f;
            #pragma unroll
            for (int k4 = 0; k4 < 32; k4 += 4) {
                float4 q = *(const float4*)&sp[lane * 36 + k4];
                q0 += q.x; q1 += q.y; q2 += q.z; q3 += q.w;
            }
            float cs = (q0 + q1) + (q2 + q3);
            stage[warp * 129 + cc * 32 + lane] = gelu_tanh(fmaf(Dd, rv, cs));
            __syncwarp();
        }
        __syncthreads();
        #pragma unroll
        for (int p = 0; p < 2; ++p) {
            int l = lrel + p * 64;
            float v0 = stage[(2 * dp) * 129 + l];
            float v1 = stage[(2 * dp + 1) * 129 + l];
            u32 lo0, lo1;
            u32 h0 = bfsplit(v0, lo0);
            u32 h1 = bfsplit(v1, lo1);
            size_t row = ((size_t)b * LTT + c4 * 128 + l) * 128 + (dbase >> 1) + dp;
            g_yh[row] = h0 | (h1 << 16);
            g_yl[row] = lo0 | (lo1 << 16);
        }
        __syncthreads();
    }
    // tail: l = 2048..2054
    {
        float rv = 0.f;
        if (lane < 7) rv = fmaf(u[2048 + lane] - mean, scl, bet);
        #pragma unroll
        for (int j = 0; j < 7; ++j) {
            float uv = __shfl_sync(0xffffffffu, rv, j);
            ull uv2 = pk2(uv, uv);
            ull t   = f2fma(nai2, si2, uv2);
            ull nsr = f2fma(ar2, sr2, t);
            ull nsi = f2fma(ai2, sr2, f2mul(ar2, si2));
            sr2 = nsr; si2 = nsi;
            ull pr = f2fma(cr2, sr2, f2mul(nci2, si2));
            float px, py; up2(pr, px, py);
            sp[j * 36 + lane] = px + py;
        }
        __syncwarp();
        if (lane < 7) {
            float q0 = 0.f, q1 = 0.f, q2 = 0.f, q3 = 0.f;
            #pragma unroll
            for (int k4 = 0; k4 < 32; k4 += 4) {
                float4 q = *(const float4*)&sp[lane * 36 + k4];
                q0 += q.x; q1 += q.y; q2 += q.z; q3 += q.w;
            }
            float cs = (q0 + q1) + (q2 + q3);
            stage[warp * 129 + lane] = gelu_tanh(fmaf(Dd, rv, cs));
        }
        __syncthreads();
        if (lrel < 7) {
            float v0 = stage[(2 * dp) * 129 + lrel];
            float v1 = stage[(2 * dp + 1) * 129 + lrel];
            u32 lo0, lo1;
            u32 h0 = bfsplit(v0, lo0);
            u32 h1 = bfsplit(v1, lo1);
            size_t row = ((size_t)b * LTT + 2048 + lrel) * 128 + (dbase >> 1) + dp;
            g_yh[row] = h0 | (h1 << 16);
            g_yl[row] = lo0 | (lo1 << 16);
        }
    }
}

// ---- out-proj GEMM: split-bf16 HMMA (R6 mainloop) + parallel coalesced epilogue ----
extern "C" __global__ void __launch_bounds__(256) k_gemm(
        const float* __restrict__ ob, const float* __restrict__ pg,
        const float* __restrict__ pb, int apply_bn, int layer) {
    extern __shared__ u32 gsm[];
    // Ah: [0,4608)  Al: [4608,9216)  Bh: [9216,11520)  Bl: [11520,13824)   (u32 idx)
    const int bb = blockIdx.z, et = blockIdx.y, lt = blockIdx.x;
    const int e0 = et * 64, l0 = lt * 64;
    const int tid = threadIdx.x;
    const int wid = tid >> 5, lane = tid & 31;
    const int h = wid >> 2, wq = wid & 3;
    const int g = lane >> 2, t = lane & 3;
    const u32* Wh = g_wh[layer];
    const u32* Wl = g_wl[layer];
    float acc[4][2][4];
    #pragma unroll
    for (int mf = 0; mf < 4; ++mf)
        #pragma unroll
        for (int nf = 0; nf < 2; ++nf)
            #pragma unroll
            for (int r = 0; r < 4; ++r) acc[mf][nf][r] = 0.f;

    const int r_all = tid >> 3, j4 = (tid & 7) * 4;
    for (int kc = 0; kc < 4; ++kc) {
        const int kb2 = kc * 32;
        __syncthreads();
        #pragma unroll
        for (int p = 0; p < 4; ++p) {
            int row = p * 32 + r_all;      // 0..127
            int hh = row >> 6, r = row & 63;
            int eg = e0 + (hh ? 256 : 0) + r;
            *(uint4*)&gsm[(hh * 64 + r) * 36 + j4] =
                *(const uint4*)&Wh[(size_t)eg * 128 + kb2 + j4];
            *(uint4*)&gsm[4608 + (hh * 64 + r) * 36 + j4] =
                *(const uint4*)&Wl[(size_t)eg * 128 + kb2 + j4];
        }
        #pragma unroll
        for (int p = 0; p < 2; ++p) {
            int lrow = p * 32 + r_all;     // 0..63
            size_t yrow = ((size_t)bb * LTT + l0 + lrow) * 128 + kb2 + j4;
            *(uint4*)&gsm[9216 + lrow * 36 + j4] = *(const uint4*)&g_yh[yrow];
            *(uint4*)&gsm[11520 + lrow * 36 + j4] = *(const uint4*)&g_yl[yrow];
        }
        __syncthreads();
        const u32* A_h = gsm + h * 2304;
        const u32* A_l = gsm + 4608 + h * 2304;
        #pragma unroll
        for (int ks = 0; ks < 4; ++ks) {
            u32 ah[4][4], al[4][4], bh[2][2], bl[2][2];
            #pragma unroll
            for (int mf = 0; mf < 4; ++mf) {
                int rb = (16 * mf + g) * 36 + ks * 8 + t;
                ah[mf][0] = A_h[rb];       ah[mf][1] = A_h[rb + 288];
                ah[mf][2] = A_h[rb + 4];   ah[mf][3] = A_h[rb + 292];
                al[mf][0] = A_l[rb];       al[mf][1] = A_l[rb + 288];
                al[mf][2] = A_l[rb + 4];   al[mf][3] = A_l[rb + 292];
            }
            #pragma unroll
            for (int nf = 0; nf < 2; ++nf) {
                int nr = (wq * 16 + nf * 8 + g) * 36 + ks * 8 + t;
                bh[nf][0] = gsm[9216 + nr];  bh[nf][1] = gsm[9216 + nr + 4];
                bl[nf][0] = gsm[11520 + nr]; bl[nf][1] = gsm[11520 + nr + 4];
            }
            #pragma unroll
            for (int mf = 0; mf < 4; ++mf)
                #pragma unroll
                for (int nf = 0; nf < 2; ++nf) {
                    mma16816(acc[mf][nf], ah[mf], bh[nf]);
                    mma16816(acc[mf][nf], ah[mf], bl[nf]);
                    mma16816(acc[mf][nf], al[mf], bh[nf]);
                }
        }
    }
    __syncthreads();
    // dump both GLU halves: z1 (h==0 accs) -> zb1, z2 (h==1 accs) -> zb2
    float* zb1 = (float*)gsm;               // [64][66]
    float* zb2 = (float*)(gsm + 4224);      // [64][66]
    float* zb = h ? zb2 : zb1;
    #pragma unroll
    for (int mf = 0; mf < 4; ++mf)
        #pragma unroll
        for (int nf = 0; nf < 2; ++nf) {
            int lc = wq * 16 + nf * 8 + 2 * t;
            zb[(16 * mf + g) * 66 + lc]     = acc[mf][nf][0];
            zb[(16 * mf + g) * 66 + lc + 1] = acc[mf][nf][1];
            zb[(16 * mf + g + 8) * 66 + lc]     = acc[mf][nf][2];
            zb[(16 * mf + g + 8) * 66 + lc + 1] = acc[mf][nf][3];
        }
    __syncthreads();
    // coalesced fused epilogue: all 256 threads; thread = (row dd, 16-l segment)
    {
        const int dd = tid >> 2, seg = tid & 3;
        const int d = e0 + dd;
        const int lbase = l0 + seg * 16;
        float bz1 = ob[d], bz2 = ob[DM + d];
        float mn = 0.f, sc = 1.f, bt = 0.f;
        if (apply_bn) { mn = g_mean[d]; sc = g_rstd[d] * pg[d]; bt = pb[d]; }
        float* hrow = g_h + ((size_t)bb * DM + d) * LTP;
        const float* z1r = zb1 + dd * 66 + seg * 16;
        const float* z2r = zb2 + dd * 66 + seg * 16;
        float s = 0.f, s2 = 0.f;
        #pragma unroll
        for (int i = 0; i < 16; i += 4) {
            int lg = lbase + i;
            if (lg + 3 < LT) {
                float4 hv = *(const float4*)&hrow[lg];
                float hn0, hn1, hn2, hn3;
                {
                    float z1 = z1r[i] + bz1,     z2 = z2r[i] + bz2;
                    hn0 = fmaf(hv.x - mn, sc, bt) + z1 * sigm(z2);
                }
                {
                    float z1 = z1r[i + 1] + bz1, z2 = z2r[i + 1] + bz2;
                    hn1 = fmaf(hv.y - mn, sc, bt) + z1 * sigm(z2);
                }
                {
                    float z1 = z1r[i + 2] + bz1, z2 = z2r[i + 2] + bz2;
                    hn2 = fmaf(hv.z - mn, sc, bt) + z1 * sigm(z2);
                }
                {
                    float z1 = z1r[i + 3] + bz1, z2 = z2r[i + 3] + bz2;
                    hn3 = fmaf(hv.w - mn, sc, bt) + z1 * sigm(z2);
                }
                *(float4*)&hrow[lg] = make_float4(hn0, hn1, hn2, hn3);
                s += (hn0 + hn1) + (hn2 + hn3);
                s2 = fmaf(hn0, hn0, s2); s2 = fmaf(hn1, hn1, s2);
                s2 = fmaf(hn2, hn2, s2); s2 = fmaf(hn3, hn3, s2);
            } else {
                #pragma unroll
                for (int k = 0; k < 4; ++k) {
                    int l = lg + k;
                    if (l < LT) {
                        float z1 = z1r[i + k] + bz1, z2 = z2r[i + k] + bz2;
                        float hn = fmaf(hrow[l] - mn, sc, bt) + z1 * sigm(z2);
                        hrow[l] = hn;
                        s += hn; s2 = fmaf(hn, hn, s2);
                    }
                }
            }
        }
        s  += __shfl_xor_sync(0xffffffffu, s, 1);
        s  += __shfl_xor_sync(0xffffffffu, s, 2);
        s2 += __shfl_xor_sync(0xffffffffu, s2, 1);
        s2 += __shfl_xor_sync(0xffffffffu, s2, 2);
        if (seg == 0) {
            int slot = lt * 32 + bb;
            g_bnp0[d * NT + slot] = s;
            g_bnp1[d * NT + slot] = s2;
        }
    }
}

// ---------------- BN finalize ----------------
__global__ void k_bnfin() {
    int d = blockIdx.x, tid = threadIdx.x;   // 256 threads
    float s = 0.f, s2 = 0.f;
    for (int i = tid; i < NT; i += 256) {
        s  += g_bnp0[d * NT + i];
        s2 += g_bnp1[d * NT + i];
    }
    __shared__ float sh1[256], sh2[256];
    sh1[tid] = s; sh2[tid] = s2;
    __syncthreads();
    for (int o = 128; o; o >>= 1) {
        if (tid < o) { sh1[tid] += sh1[tid + o]; sh2[tid] += sh2[tid + o]; }
        __syncthreads();
    }
    if (tid == 0) {
        float n = (float)(BB * LT);
        float mean = sh1[0] / n;
        float var = sh2[0] / n - mean * mean;
        g_mean[d] = mean;
        g_rstd[d] = rsqrtf(var + 1e-5f);
    }
}

// ---------------- head (applies final BN lazily) ----------------
__global__ void k_head(const float* __restrict__ W1, const float* __restrict__ b1,
                       const float* __restrict__ W2, const float* __restrict__ b2,
                       const float* __restrict__ pg, const float* __restrict__ pb,
                       float* __restrict__ out) {
    int i = blockIdx.x, b = blockIdx.y, tid = threadIdx.x;  // 128 threads
    int l = (LL - 1) + i;
    float acc = b1[tid];
    const float* Hb = g_h + (size_t)b * DM * LTP + l;
    #pragma unroll 4
    for (int d = 0; d < DM; ++d) {
        float v = fmaf(Hb[(size_t)d * LTP] - g_mean[d], g_rstd[d] * pg[d], pb[d]);
        acc = fmaf(v, W1[d * 128 + tid], acc);
    }
    float sv = acc * sigm(acc);
    __shared__ float sh[128];
    sh[tid] = sv * W2[tid];
    __syncthreads();
    for (int o = 64; o; o >>= 1) {
        if (tid < o) sh[tid] += sh[tid + o];
        __syncthreads();
    }
    if (tid == 0) out[b * HH + i] = sh[0] + b2[0];
}

// ---------------- launch ----------------
extern "C" void kernel_launch(void* const* d_in, const int* in_sizes, int n_in,
                              void* d_out, int out_size) {
    const float* x_past   = (const float*)d_in[0];
    const float* noisy    = (const float*)d_in[1];
    const float* t        = (const float*)d_in[2];
    const float* x_future = (const float*)d_in[3];
    const float* stat     = (const float*)d_in[4];
    const float* freqs    = (const float*)d_in[5];
    const float* phases   = (const float*)d_in[6];
    const float* in_W     = (const float*)d_in[7];
    const float* in_b     = (const float*)d_in[8];
    const float* tm_W1    = (const float*)d_in[9];
    const float* tm_b1    = (const float*)d_in[10];
    const float* tm_W2    = (const float*)d_in[11];
    const float* tm_b2    = (const float*)d_in[12];
    const float* log_dt   = (const float*)d_in[13];
    const float* A_re     = (const float*)d_in[14];
    const float* A_im     = (const float*)d_in[15];
    const float* C_re     = (const float*)d_in[16];
    const float* C_im     = (const float*)d_in[17];
    const float* Dv       = (const float*)d_in[18];
    const float* out_W    = (const float*)d_in[19];
    const float* out_b    = (const float*)d_in[20];
    const float* bn_g     = (const float*)d_in[21];
    const float* bn_b     = (const float*)d_in[22];
    const float* hW1      = (const float*)d_in[23];
    const float* hb1      = (const float*)d_in[24];
    const float* hW2      = (const float*)d_in[25];
    const float* hb2      = (const float*)d_in[26];
    float* out = (float*)d_out;

    cudaFuncSetAttribute(k_scan, cudaFuncAttributeMaxDynamicSharedMemorySize, SCAN_SMEM);
    cudaFuncSetAttribute(k_gemm, cudaFuncAttributeMaxDynamicSharedMemorySize, GEMM_SMEM);

    k_timemlp<<<BB, 256>>>(t, freqs, phases, tm_W1, tm_b1, tm_W2, tm_b2);
    k_wprep<<<1024, 256>>>(out_W);
    k_zpad<<<912, 256>>>();
    k_inproj<<<dim3(65, 4, BB), 256>>>(x_past, noisy, x_future, stat, in_W, in_b);

    for (int i = 0; i < NLAYERS; ++i) {
        const float* pg = (i == 0) ? bn_g : bn_g + (i - 1) * DM;
        const float* pb = (i == 0) ? bn_b : bn_b + (i - 1) * DM;
        k_scan<<<256, 1024, SCAN_SMEM>>>(log_dt + i * DM,
                                         A_re + (size_t)i * DM * DS, A_im + (size_t)i * DM * DS,
                                         C_re + (size_t)i * DM * DS, C_im + (size_t)i * DM * DS,
                                         Dv + i * DM, pg, pb, i > 0);
        k_gemm<<<dim3(33, 4, BB), 256, GEMM_SMEM>>>(out_b + i * 2 * DM, pg, pb, i > 0, i);
        k_bnfin<<<DM, 256>>>();
    }
    k_head<<<dim3(HH, BB), 128>>>(hW1, hb1, hW2, hb2, bn_g + 3 * DM, bn_b + 3 * DM, out);
}